// round 13
// baseline (speedup 1.0000x reference)
#include <cuda_runtime.h>
#include <cstdint>
#include <math.h>

// MMD loss: B=4096, D=256, N=2B=8192.
// loss = (1/B^2) * sum_{i,j} sign(i,j) * K(i,j),  sign = +1 same block, -1 cross.
// K(i,j) = sum_{m=0..4} exp(-L2_ij/(bw*2^m)),  bw = (sum L2)/(N^2-N)/4.
// u = exp2(L2*negc2) -> K = u+u^2+u^4+u^8+u^16.
// INT8 IMMA m16n8k32 Gram tiles; per-row symmetric quantization; sq/bandwidth
// from DEQUANTIZED values (L2(i,i)==0 exactly). Whole-tile double buffering
// (1 CTA/SM, 160KB smem) with the PREVIOUS tile's Gaussian epilogue dovetailed
// into the CURRENT tile's mma stream (ping-pong accumulator sets).

#define DDIM 256
#define CHUNK_B 10240           // 128 rows x 80B (64 int8 + 16 pad)
#define TILE_B  40960           // 4 chunks, contiguous per 128-row tile
#define MATS    81920u          // A+B per buffer

__device__ char   g_i8[64 * TILE_B];   // quantized chunked [src; tgt]
__device__ float  g_scale[8192];       // per-row dequant scale
__device__ float  g_sq[8192];
__device__ float  g_sqn[8192];         // sq * negc2
__device__ float  g_m2sn[8192];        // -2 * scale * negc2
__device__ float  g_colsum[256];
__device__ float  g_negc2;
__device__ double g_accum;

// SMEM: [buf0: A 40K | B 40K][buf1: A | B][consts 2K][mbar 16][red 32]
#define SM_AB(b)   ((uint32_t)(b) * MATS)
#define SM_CONST   163840u
#define SM_MBAR    165888u
#define SM_RED     165904u
#define SM_TOTAL   165952

// ---------------- helpers ---------------------------------------------------
__device__ __forceinline__ uint32_t smem_u32(const void* p) {
    uint32_t a;
    asm("{ .reg .u64 t; cvta.to.shared.u64 t, %1; cvt.u32.u64 %0, t; }" : "=r"(a) : "l"(p));
    return a;
}
__device__ __forceinline__ void ldsm4(uint32_t* r, uint32_t addr) {
    asm volatile("ldmatrix.sync.aligned.m8n8.x4.shared.b16 {%0,%1,%2,%3}, [%4];"
                 : "=r"(r[0]), "=r"(r[1]), "=r"(r[2]), "=r"(r[3]) : "r"(addr));
}
__device__ __forceinline__ void mma16832s8(int* c, const uint32_t* a, const uint32_t* b) {
    asm volatile(
        "mma.sync.aligned.m16n8k32.row.col.s32.s8.s8.s32 "
        "{%0,%1,%2,%3}, {%4,%5,%6,%7}, {%8,%9}, {%0,%1,%2,%3};"
        : "+r"(c[0]), "+r"(c[1]), "+r"(c[2]), "+r"(c[3])
        : "r"(a[0]), "r"(a[1]), "r"(a[2]), "r"(a[3]), "r"(b[0]), "r"(b[1]));
}
__device__ __forceinline__ void bulk_g2s(uint32_t dst, const void* src,
                                         uint32_t bytes, uint32_t mbar) {
    asm volatile(
        "cp.async.bulk.shared::cluster.global.mbarrier::complete_tx::bytes [%0], [%1], %2, [%3];"
        :: "r"(dst), "l"(src), "r"(bytes), "r"(mbar) : "memory");
}
#define MB_INIT(mb, c) asm volatile("mbarrier.init.shared.b64 [%0], %1;" :: "r"(mb), "r"(c) : "memory")
#define MB_EXPECT_TX(mb, n) asm volatile("mbarrier.arrive.expect_tx.shared.b64 _, [%0], %1;" :: "r"(mb), "r"(n) : "memory")
#define MB_WAIT(mb, par) do {                                                 \
    uint32_t _m = (mb), _p = (par), _d;                                       \
    asm volatile("{\n\t.reg .pred p;\n\t"                                     \
        "mbarrier.try_wait.parity.acquire.cta.shared::cta.b64 p, [%1], %2;\n\t" \
        "selp.b32 %0, 1, 0, p;\n\t}" : "=r"(_d) : "r"(_m), "r"(_p) : "memory"); \
    if (!_d) {                                                                \
        asm volatile("{\n\t.reg .pred P1;\n\t"                                \
            "W_%=:\n\t"                                                       \
            "mbarrier.try_wait.parity.acquire.cta.shared::cta.b64 P1, [%0], %1, 0x989680;\n\t" \
            "@P1 bra.uni D_%=;\n\t"                                           \
            "bra.uni W_%=;\n\t"                                               \
            "D_%=:\n\t}" :: "r"(_m), "r"(_p) : "memory");                     \
    }                                                                         \
} while (0)

__device__ __forceinline__ float fast_ex2(float x) {
    float r;
    asm("ex2.approx.ftz.f32 %0, %1;" : "=f"(r) : "f"(x));
    return r;
}
typedef unsigned long long u64t;
__device__ __forceinline__ u64t f2pack(float lo, float hi) {
    u64t r; asm("mov.b64 %0, {%1, %2};" : "=l"(r) : "f"(lo), "f"(hi)); return r;
}
__device__ __forceinline__ void f2unpack(u64t v, float& lo, float& hi) {
    asm("mov.b64 {%0, %1}, %2;" : "=f"(lo), "=f"(hi) : "l"(v));
}
__device__ __forceinline__ u64t f2fma(u64t a, u64t b, u64t c) {
    u64t d; asm("fma.rn.f32x2 %0, %1, %2, %3;" : "=l"(d) : "l"(a), "l"(b), "l"(c)); return d;
}
__device__ __forceinline__ void tri_decode(int idx, int NT, int& ti, int& tj) {
    float fn = (float)NT + 0.5f;
    int a = (int)(fn - sqrtf(fn * fn - 2.0f * (float)idx));
    while (a * NT - (a * (a - 1)) / 2 > idx) --a;
    while ((a + 1) * NT - ((a + 1) * a) / 2 <= idx) ++a;
    ti = a;
    tj = a + (idx - (a * NT - (a * (a - 1)) / 2));
}

// ---------------------------------------------------------------------------
__global__ void k_zero() {
    g_colsum[threadIdx.x] = 0.f;
    if (threadIdx.x == 0) g_accum = 0.0;
}

// ---------------------------------------------------------------------------
__global__ void k_prep(const float* __restrict__ src,
                       const float* __restrict__ tgt, int B) {
    __shared__ float scol[256];
    scol[threadIdx.x] = 0.f;
    __syncthreads();

    const int warp = threadIdx.x >> 5;
    const int lane = threadIdx.x & 31;
    const int rowBase = blockIdx.x * 64 + warp * 8;

    float c0 = 0.f, c1 = 0.f, c2 = 0.f, c3 = 0.f;
    float c4 = 0.f, c5 = 0.f, c6 = 0.f, c7 = 0.f;

    const int ca = lane * 4;
    const int cb = 128 + lane * 4;

    #pragma unroll
    for (int r = 0; r < 8; ++r) {
        const int row = rowBase + r;
        const float* rp = (row < B) ? (src + (size_t)row * DDIM)
                                    : (tgt + (size_t)(row - B) * DDIM);
        float4 v0 = *(const float4*)(rp + ca);
        float4 v1 = *(const float4*)(rp + cb);

        float am = fmaxf(fmaxf(fmaxf(fabsf(v0.x), fabsf(v0.y)),
                               fmaxf(fabsf(v0.z), fabsf(v0.w))),
                         fmaxf(fmaxf(fabsf(v1.x), fabsf(v1.y)),
                               fmaxf(fabsf(v1.z), fabsf(v1.w))));
        #pragma unroll
        for (int o = 16; o; o >>= 1)
            am = fmaxf(am, __shfl_xor_sync(0xffffffffu, am, o));

        const float s   = am * (1.0f / 127.0f);
        const float inv = (am > 0.f) ? 127.0f / am : 0.f;

        int q0 = __float2int_rn(v0.x * inv), q1 = __float2int_rn(v0.y * inv);
        int q2 = __float2int_rn(v0.z * inv), q3 = __float2int_rn(v0.w * inv);
        int q4 = __float2int_rn(v1.x * inv), q5 = __float2int_rn(v1.y * inv);
        int q6 = __float2int_rn(v1.z * inv), q7 = __float2int_rn(v1.w * inv);

        uint32_t pk0 = (uint32_t)(q0 & 0xff) | ((uint32_t)(q1 & 0xff) << 8)
                     | ((uint32_t)(q2 & 0xff) << 16) | ((uint32_t)(q3 & 0xff) << 24);
        uint32_t pk1 = (uint32_t)(q4 & 0xff) | ((uint32_t)(q5 & 0xff) << 8)
                     | ((uint32_t)(q6 & 0xff) << 16) | ((uint32_t)(q7 & 0xff) << 24);

        const int tile = row >> 7, rl = row & 127;
        size_t base = (size_t)tile * TILE_B + (size_t)rl * 80;
        *(uint32_t*)(g_i8 + base + (size_t)(ca >> 6) * CHUNK_B + (ca & 63)) = pk0;
        *(uint32_t*)(g_i8 + base + (size_t)(cb >> 6) * CHUNK_B + (cb & 63)) = pk1;

        float d0 = (float)q0 * s, d1 = (float)q1 * s, d2 = (float)q2 * s, d3 = (float)q3 * s;
        float d4 = (float)q4 * s, d5 = (float)q5 * s, d6 = (float)q6 * s, d7 = (float)q7 * s;

        float ss = d0*d0 + d1*d1 + d2*d2 + d3*d3 + d4*d4 + d5*d5 + d6*d6 + d7*d7;
        #pragma unroll
        for (int o = 16; o; o >>= 1) ss += __shfl_xor_sync(0xffffffffu, ss, o);
        if (lane == 0) { g_sq[row] = ss; g_scale[row] = s; }

        c0 += d0; c1 += d1; c2 += d2; c3 += d3;
        c4 += d4; c5 += d5; c6 += d6; c7 += d7;
    }

    atomicAdd(&scol[lane * 4 + 0], c0);
    atomicAdd(&scol[lane * 4 + 1], c1);
    atomicAdd(&scol[lane * 4 + 2], c2);
    atomicAdd(&scol[lane * 4 + 3], c3);
    atomicAdd(&scol[128 + lane * 4 + 0], c4);
    atomicAdd(&scol[128 + lane * 4 + 1], c5);
    atomicAdd(&scol[128 + lane * 4 + 2], c6);
    atomicAdd(&scol[128 + lane * 4 + 3], c7);
    __syncthreads();
    atomicAdd(&g_colsum[threadIdx.x], scol[threadIdx.x]);
}

// ---------------------------------------------------------------------------
__global__ void k_bw(int B) {
    const int N = 2 * B;
    __shared__ double sh[256];
    const int t = threadIdx.x;

    double s = 0.0;
    for (int i = t; i < N; i += 256) s += (double)g_sq[i];
    sh[t] = s;
    __syncthreads();
    for (int st = 128; st; st >>= 1) {
        if (t < st) sh[t] += sh[t + st];
        __syncthreads();
    }
    double sumsq = sh[0];
    __syncthreads();

    float c = g_colsum[t];
    sh[t] = (double)c * (double)c;
    __syncthreads();
    for (int st = 128; st; st >>= 1) {
        if (t < st) sh[t] += sh[t + st];
        __syncthreads();
    }
    if (t == 0) {
        double ssq   = sh[0];
        double sumL2 = 2.0 * (double)N * sumsq - 2.0 * ssq;
        double bw    = sumL2 / ((double)N * (double)N - (double)N);
        bw /= 4.0;
        g_negc2 = (float)(-1.4426950408889634 / (16.0 * bw));
        g_accum = 0.0;
    }
}

// pre-scale epilogue constants by negc2
__global__ void k_scale() {
    const int i = blockIdx.x * 256 + threadIdx.x;
    const float nc = g_negc2;
    g_sqn[i]  = g_sq[i] * nc;
    g_m2sn[i] = -2.f * g_scale[i] * nc;
}

// ---------------------------------------------------------------------------
// Macros for the dovetailed mainloop/epilogue
#define KS_STEP(ACCM, ks) do {                                                \
    const uint32_t _off = (uint32_t)((((ks) >> 1) * CHUNK_B) + (((ks) & 1) * 32)); \
    uint32_t af[2][4], bf_[4][4];                                             \
    ldsm4(af[0], aBse + aRowOff[0] + _off);                                   \
    ldsm4(af[1], aBse + aRowOff[1] + _off);                                   \
    ldsm4(bf_[0], bBse + bRowOff[0] + _off);                                  \
    ldsm4(bf_[1], bBse + bRowOff[1] + _off);                                  \
    ldsm4(bf_[2], bBse + bRowOff[2] + _off);                                  \
    ldsm4(bf_[3], bBse + bRowOff[3] + _off);                                  \
    _Pragma("unroll")                                                         \
    for (int _m = 0; _m < 2; ++_m)                                            \
        _Pragma("unroll")                                                     \
        for (int _p = 0; _p < 4; ++_p) {                                      \
            mma16832s8(ACCM[_m][2 * _p],     af[_m], &bf_[_p][0]);            \
            mma16832s8(ACCM[_m][2 * _p + 1], af[_m], &bf_[_p][2]);            \
        }                                                                     \
} while (0)

#define EPI_SLICE(ACCE, e) do {                                               \
    const int _m = (e) >> 4, _n = ((e) >> 1) & 7, _h = (e) & 1;               \
    const int _c0 = wcol + _n * 8 + (lane & 3) * 2;                           \
    u64t _sqbn = *(const u64t*)(cSqbn + _c0);                                 \
    u64t _m2sn = *(const u64t*)(cM2sn + _c0);                                 \
    float _f0 = __int2float_rn(ACCE[_m][_n][2 * _h]);                         \
    float _f1 = __int2float_rn(ACCE[_m][_n][2 * _h + 1]);                     \
    u64t _dp   = f2pack(_f0, _f1);                                            \
    u64t _tpd  = f2fma(_dp, siDup[_m * 2 + _h], ZERO);                        \
    u64t _sums = f2fma(sqanDup[_m * 2 + _h], ONE, _sqbn);                     \
    u64t _xp   = f2fma(_tpd, _m2sn, _sums);                                   \
    float _x0, _x1; f2unpack(_xp, _x0, _x1);                                  \
    u64t _up = f2pack(fast_ex2(_x0), fast_ex2(_x1));                          \
    u64t _a  = f2fma(_up, _up, _up);                                          \
    u64t _u2 = f2fma(_up, _up, ZERO);                                         \
    u64t _u4 = f2fma(_u2, _u2, ZERO);                                         \
    u64t _b  = f2fma(_u4, _u4, _u4);                                          \
    u64t _u8 = f2fma(_u4, _u4, ZERO);                                         \
    tsp = f2fma(_u8, _u8, tsp);                                               \
    tsp = f2fma(_a, ONE, tsp);                                                \
    tsp = f2fma(_b, ONE, tsp);                                                \
} while (0)

#define HOIST_ROW_CONSTS() do {                                               \
    _Pragma("unroll")                                                         \
    for (int _m = 0; _m < 2; ++_m)                                            \
        _Pragma("unroll")                                                     \
        for (int _h = 0; _h < 2; ++_h) {                                      \
            const int _row = wrow + _m * 16 + (lane >> 2) + _h * 8;           \
            float _va = cSqan[_row], _vs = cSi[_row];                         \
            sqanDup[_m * 2 + _h] = f2pack(_va, _va);                          \
            siDup[_m * 2 + _h]   = f2pack(_vs, _vs);                          \
        }                                                                     \
} while (0)

#define ZERO_ACC(ACCM) do {                                                   \
    _Pragma("unroll")                                                         \
    for (int _m = 0; _m < 2; ++_m)                                            \
        _Pragma("unroll")                                                     \
        for (int _n = 0; _n < 8; ++_n)                                        \
            _Pragma("unroll")                                                 \
            for (int _r = 0; _r < 4; ++_r) ACCM[_m][_n][_r] = 0;              \
} while (0)

#define DO_TILE(ACCM, ACCE, DOEPI) do {                                       \
    ZERO_ACC(ACCM);                                                           \
    if (DOEPI) { HOIST_ROW_CONSTS(); tsp = ZERO; }                            \
    _Pragma("unroll")                                                         \
    for (int _ks = 0; _ks < 8; ++_ks) {                                       \
        KS_STEP(ACCM, _ks);                                                   \
        if (DOEPI) {                                                          \
            _Pragma("unroll")                                                 \
            for (int _q = 0; _q < 4; ++_q) EPI_SLICE(ACCE, _ks * 4 + _q);     \
        }                                                                     \
    }                                                                         \
} while (0)

#define TAIL_EPI(ACCE) do {                                                   \
    HOIST_ROW_CONSTS(); tsp = ZERO;                                           \
    _Pragma("unroll")                                                         \
    for (int _e = 0; _e < 32; ++_e) EPI_SLICE(ACCE, _e);                      \
} while (0)

#define REDUCE_PREV() do {                                                    \
    float _tl, _th; f2unpack(tsp, _tl, _th);                                  \
    float _ts = _tl + _th;                                                    \
    _Pragma("unroll")                                                         \
    for (int _o = 16; _o; _o >>= 1) _ts += __shfl_xor_sync(0xffffffffu, _ts, _o); \
    float* _red = (float*)(smem + SM_RED);                                    \
    if (lane == 0) _red[wid] = _ts;                                           \
    __syncthreads();                                                          \
    if (wid == 0) {                                                           \
        float _v = (lane < 8) ? _red[lane] : 0.f;                             \
        _Pragma("unroll")                                                     \
        for (int _o = 4; _o; _o >>= 1) _v += __shfl_xor_sync(0xffffffffu, _v, _o); \
        if (lane == 0) {                                                      \
            bool _si = (prevTi * 128) < B, _sj = (prevTj * 128) < B;          \
            float _w = (prevTi == prevTj) ? 1.f : 2.f;                        \
            float _sg = (_si == _sj) ? _w : -_w;                              \
            atomicAdd(&g_accum, (double)(_v * _sg));                          \
        }                                                                     \
    }                                                                         \
} while (0)

#define STAGE(tix, tjx, b) do {                                               \
    const uint32_t _mb = sbase + SM_MBAR + (uint32_t)(b) * 8;                 \
    MB_EXPECT_TX(_mb, 2 * TILE_B);                                            \
    bulk_g2s(sbase + SM_AB(b),          g_i8 + (size_t)(tix) * TILE_B, TILE_B, _mb); \
    bulk_g2s(sbase + SM_AB(b) + TILE_B, g_i8 + (size_t)(tjx) * TILE_B, TILE_B, _mb); \
} while (0)

#define WRITE_CONSTS(tix, tjx) do {                                           \
    if (t < 128) {                                                            \
        cSqan[t] = g_sqn[(tix) * 128 + t];                                    \
        cSi[t]   = g_scale[(tix) * 128 + t];                                  \
        cSqbn[t] = g_sqn[(tjx) * 128 + t];                                    \
        cM2sn[t] = g_m2sn[(tjx) * 128 + t];                                   \
    }                                                                         \
} while (0)

// ---------------------------------------------------------------------------
__global__ void __launch_bounds__(256, 1) k_mmd(int B, int NT, int ntri) {
    extern __shared__ __align__(16) char smem[];
    const uint32_t sbase = smem_u32(smem);
    const int t = threadIdx.x;
    const int wid = t >> 5, lane = t & 31;
    const int g = gridDim.x;

    float* cSqan = (float*)(smem + SM_CONST);
    float* cSi   = (float*)(smem + SM_CONST + 512);
    float* cSqbn = (float*)(smem + SM_CONST + 1024);
    float* cM2sn = (float*)(smem + SM_CONST + 1536);

    if (t == 0) {
        MB_INIT(sbase + SM_MBAR, 1);
        MB_INIT(sbase + SM_MBAR + 8, 1);
    }
    __syncthreads();

    const int wrow = (wid & 3) * 32;
    const int wcol = (wid >> 2) * 64;
    const uint32_t aThr = (uint32_t)(((lane >> 3) & 1) * 8 + (lane & 7)) * 80
                        + (uint32_t)(lane >> 4) * 16;
    const uint32_t bThr = (uint32_t)((lane >> 4) * 8 + (lane & 7)) * 80
                        + (uint32_t)((lane >> 3) & 1) * 16;
    uint32_t aRowOff[2], bRowOff[4];
    #pragma unroll
    for (int m = 0; m < 2; ++m) aRowOff[m] = (uint32_t)(wrow + m * 16) * 80 + aThr;
    #pragma unroll
    for (int p = 0; p < 4; ++p) bRowOff[p] = (uint32_t)(wcol + p * 16) * 80 + bThr;

    int curIdx = blockIdx.x;
    if (curIdx >= ntri) return;
    int ti, tj;
    tri_decode(curIdx, NT, ti, tj);

    int ph0 = 0, ph1 = 0;
    // initial staging: tile0 -> buf0, tile1 -> buf1
    if (t == 0) {
        STAGE(ti, tj, 0);
        if (curIdx + g < ntri) {
            int a2, b2;
            tri_decode(curIdx + g, NT, a2, b2);
            STAGE(a2, b2, 1);
        }
    }

    int accA[2][8][4], accB[2][8][4];
    u64t tsp = 0ull;
    u64t sqanDup[4], siDup[4];
    const u64t ZERO = 0ull;
    const u64t ONE  = f2pack(1.f, 1.f);
    int prevTi = 0, prevTj = 0;

    // ---- peel: mainloop tile0 into accA (no epilogue) ----
    {
        uint32_t aBse = sbase + SM_AB(0);
        uint32_t bBse = aBse + TILE_B;
        MB_WAIT(sbase + SM_MBAR, 0); ++ph0;
        DO_TILE(accA, accA, false);
        __syncthreads();
        WRITE_CONSTS(ti, tj);
        if (t == 0 && curIdx + 2 * g < ntri) {
            int a2, b2;
            tri_decode(curIdx + 2 * g, NT, a2, b2);
            STAGE(a2, b2, 0);
        }
        __syncthreads();
    }
    prevTi = ti; prevTj = tj;
    curIdx += g;
    int bufc = 1;
    bool p = true;   // true: mainloop->accB, epilogue from accA
    bool prevValid = true;

    while (prevValid) {
        if (curIdx < ntri) {
            tri_decode(curIdx, NT, ti, tj);
            uint32_t aBse = sbase + SM_AB(bufc);
            uint32_t bBse = aBse + TILE_B;
            if (bufc == 0) { MB_WAIT(sbase + SM_MBAR,     ph0 & 1); ++ph0; }
            else           { MB_WAIT(sbase + SM_MBAR + 8, ph1 & 1); ++ph1; }

            if (p) DO_TILE(accB, accA, true);
            else   DO_TILE(accA, accB, true);

            REDUCE_PREV();
            __syncthreads();
            WRITE_CONSTS(ti, tj);
            if (t == 0 && curIdx + 2 * g < ntri) {
                int a2, b2;
                tri_decode(curIdx + 2 * g, NT, a2, b2);
                STAGE(a2, b2, bufc);
            }
            __syncthreads();

            prevTi = ti; prevTj = tj;
            curIdx += g;
            bufc ^= 1;
            p = !p;
        } else {
            // tail: epilogue-only of prev (acc selected like combined's ACCE)
            if (p) TAIL_EPI(accA);
            else   TAIL_EPI(accB);
            REDUCE_PREV();
            prevValid = false;
        }
    }
}

// ---------------------------------------------------------------------------
__global__ void k_final(float* out, int B) {
    out[0] = (float)(g_accum / ((double)B * (double)B));
}

// ---------------------------------------------------------------------------
extern "C" void kernel_launch(void* const* d_in, const int* in_sizes, int n_in,
                              void* d_out, int out_size) {
    const float* src = (const float*)d_in[0];
    const float* tgt = (const float*)d_in[1];
    const int B = in_sizes[0] / DDIM;   // 4096
    const int N = 2 * B;                // 8192
    const int NT = N / 128;             // 64

    cudaFuncSetAttribute(k_mmd, cudaFuncAttributeMaxDynamicSharedMemorySize, SM_TOTAL);

    k_zero<<<1, 256>>>();
    k_prep<<<N / 64, 256>>>(src, tgt, B);
    k_bw<<<1, 256>>>(B);
    k_scale<<<N / 256, 256>>>();
    const int ntri = NT * (NT + 1) / 2; // 2080
    const int ncta = (ntri < 148) ? ntri : 148;
    k_mmd<<<ncta, 256, SM_TOTAL>>>(B, NT, ntri);
    k_final<<<1, 1>>>((float*)d_out, B);
}